// round 16
// baseline (speedup 1.0000x reference)
#include <cuda_runtime.h>
#include <cuda_fp16.h>
#include <cstdint>

// Problem constants
#define BB 8
#define HH 64
#define WW 64
#define CC 128
#define FF 128
#define KKT 9
#define OO 18
#define MTILE 128           // pixels per CTA (= GEMM M)

// deform_main dynamic SMEM layout (byte offsets)
#define A_B0 0
#define A_B1 32768
#define POS_OFF 65536                      // short4[1152] = 9216 B
#define WT_OFF  (POS_OFF + 9216)           // uint4[1152] = 18432 B
#define DYN_SMEM (WT_OFF + 18432)          // 93184 B
// offsets_hmma dynamic SMEM: two 32 KB A buffers
#define OFF_SMEM 65536

// scratch (no allocation allowed)
__device__ float g_offsets[BB * HH * WW * OO];     // [pix][18]
__device__ __half g_xh[BB * HH * WW * CC];         // fp16 mirror of x
// main-GEMM B fragments, HMMA-register layout (single fp16):
// [tap][kc][nh][i(4)][lane(32)] as uint4
#define BFRAG_N (KKT * 8 * 2 * 4 * 32 * 4)
__device__ uint32_t g_bfhi[BFRAG_N];
// offset-GEMM B fragments (N=32 padded from 18): [tap][kc][i(2)][lane] uint4
#define OBF_N (KKT * 8 * 2 * 32 * 4)
__device__ uint32_t g_obfhi[OBF_N];
__device__ uint32_t g_obflo[OBF_N];

// ---------------------------------------------------------------------------
static __device__ __forceinline__ uint32_t h2u(__half2 h) {
    return *reinterpret_cast<uint32_t*>(&h);
}
static __device__ __forceinline__ __half2 u2h(uint32_t u) {
    return *reinterpret_cast<__half2*>(&u);
}

static __device__ __forceinline__ uint32_t smem_u32(const void* p) {
    uint32_t a;
    asm("{ .reg .u64 t; cvta.to.shared.u64 t, %1; cvt.u32.u64 %0, t; }"
        : "=r"(a) : "l"(p));
    return a;
}

#define LDM4(r0, r1, r2, r3, addr) \
    asm("ldmatrix.sync.aligned.m8n8.x4.shared.b16 {%0,%1,%2,%3}, [%4];" \
        : "=r"(r0), "=r"(r1), "=r"(r2), "=r"(r3) : "r"(addr))

#define MMA16816(c0, c1, c2, c3, a0, a1, a2, a3, b0, b1) \
    asm("mma.sync.aligned.m16n8k16.row.col.f32.f16.f16.f32 " \
        "{%0,%1,%2,%3}, {%4,%5,%6,%7}, {%8,%9}, {%0,%1,%2,%3};" \
        : "+f"(c0), "+f"(c1), "+f"(c2), "+f"(c3) \
        : "r"(a0), "r"(a1), "r"(a2), "r"(a3), "r"(b0), "r"(b1))

// launch-index alignment helper so ncu -s 5 lands on deform_main
__global__ void noop_align() {}

// ---------------------------------------------------------------------------
// Kernel 0: prep — fp16 B-fragment packing (single for main, hi/lo for offs).
// ---------------------------------------------------------------------------
__global__ void prep_weights(const float* __restrict__ kern,
                             const float* __restrict__ ow) {
    int idx = blockIdx.x * 256 + threadIdx.x;
    if (idx < BFRAG_N) {
        int j    = idx & 3;
        int lane = (idx >> 2) & 31;
        int i    = (idx >> 7) & 3;
        int nh   = (idx >> 9) & 1;
        int kc   = (idx >> 10) & 7;
        int tap  = idx >> 13;
        int nt    = i * 2 + (j >> 1);
        int which = j & 1;
        int n = nh * 64 + nt * 8 + (lane >> 2);
        int k = kc * 16 + which * 8 + (lane & 3) * 2;
        float w0 = kern[((size_t)tap * CC + k) * FF + n];
        float w1 = kern[((size_t)tap * CC + k + 1) * FF + n];
        __half2 hh = __floats2half2_rn(w0, w1);
        g_bfhi[idx] = h2u(hh);
    }
    if (idx < OBF_N) {
        int j    = idx & 3;
        int lane = (idx >> 2) & 31;
        int i    = (idx >> 7) & 1;
        int kc   = (idx >> 8) & 7;
        int tap  = idx >> 11;
        int nt    = i * 2 + (j >> 1);
        int which = j & 1;
        int n = nt * 8 + (lane >> 2);
        int k = kc * 16 + which * 8 + (lane & 3) * 2;
        float w0 = 0.f, w1 = 0.f;
        if (n < OO) {
            w0 = ow[((size_t)tap * CC + k) * OO + n];
            w1 = ow[((size_t)tap * CC + k + 1) * OO + n];
        }
        __half h0 = __float2half_rn(w0);
        __half h1 = __float2half_rn(w1);
        __half l0 = __float2half_rn(w0 - __half2float(h0));
        __half l1 = __float2half_rn(w1 - __half2float(h1));
        __half2 hh = __halves2half2(h0, h1);
        __half2 ll = __halves2half2(l0, l1);
        g_obfhi[idx] = h2u(hh);
        g_obflo[idx] = h2u(ll);
    }
}

// ---------------------------------------------------------------------------
// Kernel 1: offset-predicting 3x3 conv via HMMA + fp16 x-mirror conversion.
// Each CTA converts its own 128-px stripe of x into g_xh (used later by
// deform_main; kernel-ordering guarantees completion).
// ---------------------------------------------------------------------------
__global__ __launch_bounds__(256) void offsets_hmma(
    const float* __restrict__ x,
    const float* __restrict__ ob)
{
    extern __shared__ char ap[];
    uint32_t sbase = smem_u32(ap);

    const int tid = threadIdx.x;
    const int cg = tid & 31;
    const int pg = tid >> 5;
    const int c0 = cg * 4;
    const int wid = tid >> 5;
    const int lane = tid & 31;
    const int lrow = lane & 15;
    const int lch = lane >> 4;

    int pbase = blockIdx.x * MTILE;
    int b = pbase >> 12;
    int ybase = (pbase & 4095) >> 6;

    const float* xb = x + (size_t)b * HH * WW * CC;

    // ---- fp16 mirror of this CTA's stripe ----
    {
        const float4* s4 = (const float4*)(x + (size_t)pbase * CC);
        uint2* d2 = (uint2*)(g_xh + (size_t)pbase * CC);
#pragma unroll 4
        for (int i = tid; i < MTILE * CC / 4; i += 256) {
            float4 v = s4[i];
            d2[i] = make_uint2(h2u(__floats2half2_rn(v.x, v.y)),
                               h2u(__floats2half2_rn(v.z, v.w)));
        }
    }

    float acc[4][4];
#pragma unroll
    for (int nt = 0; nt < 4; nt++)
#pragma unroll
        for (int j = 0; j < 4; j++) acc[nt][j] = 0.f;

    for (int k = 0; k < KKT; k++) {
        const uint32_t abuf = (k & 1) ? (uint32_t)A_B1 : (uint32_t)A_B0;
        int dyk = k / 3 - 1, dxk = k % 3 - 1;

#pragma unroll 4
        for (int j = 0; j < 16; j++) {
            int t = pg * 16 + j;
            int iy = ybase + (t >> 6) + dyk;
            int ix = (t & 63) + dxk;
            float4 v = make_float4(0.f, 0.f, 0.f, 0.f);
            if ((unsigned)iy < HH && (unsigned)ix < WW)
                v = *(const float4*)(xb + ((iy << 6) + ix) * CC + c0);
            __half2 h01 = __floats2half2_rn(v.x, v.y);
            __half2 h23 = __floats2half2_rn(v.z, v.w);
            uint32_t off = (uint32_t)t * 256u
                         + ((((uint32_t)c0 >> 3) ^ ((uint32_t)t & 7)) << 4)
                         + ((uint32_t)c0 & 7) * 2u;
            *(uint2*)(ap + abuf + off) = make_uint2(h2u(h01), h2u(h23));
        }
        __syncthreads();

#pragma unroll
        for (int kc = 0; kc < 8; kc++) {
            int row = wid * 16 + lrow;
            uint32_t chunk = (uint32_t)(kc * 2 + lch);
            uint32_t aoff = (uint32_t)row * 256u
                          + ((chunk ^ ((uint32_t)row & 7)) << 4);
            uint32_t a0, a1, a2, a3;
            LDM4(a0, a1, a2, a3, sbase + abuf + aoff);

            size_t bidx = (((size_t)k * 8 + kc) * 2) * 32 + lane;
            const uint4* bh = ((const uint4*)g_obfhi) + bidx;
            const uint4* bl = ((const uint4*)g_obflo) + bidx;
            uint4 bh0 = bh[0], bh1 = bh[32];
            uint4 bl0 = bl[0], bl1 = bl[32];
            uint32_t brh[8] = { bh0.x, bh0.y, bh0.z, bh0.w, bh1.x, bh1.y, bh1.z, bh1.w };
            uint32_t brl[8] = { bl0.x, bl0.y, bl0.z, bl0.w, bl1.x, bl1.y, bl1.z, bl1.w };
#pragma unroll
            for (int nt = 0; nt < 4; nt++) {
                MMA16816(acc[nt][0], acc[nt][1], acc[nt][2], acc[nt][3],
                         a0, a1, a2, a3, brh[nt * 2], brh[nt * 2 + 1]);
                MMA16816(acc[nt][0], acc[nt][1], acc[nt][2], acc[nt][3],
                         a0, a1, a2, a3, brl[nt * 2], brl[nt * 2 + 1]);
            }
        }
    }

    {
        int r0 = pbase + wid * 16 + (lane >> 2);
#pragma unroll
        for (int nt = 0; nt < 3; nt++) {
            int col = nt * 8 + (lane & 3) * 2;
            if (col < OO) {
                float2 ob2 = *(const float2*)(ob + col);
                *(float2*)(g_offsets + (size_t)r0 * OO + col) =
                    make_float2(acc[nt][0] + ob2.x, acc[nt][1] + ob2.y);
                *(float2*)(g_offsets + (size_t)(r0 + 8) * OO + col) =
                    make_float2(acc[nt][2] + ob2.x, acc[nt][3] + ob2.y);
            }
        }
    }
}

// ---------------------------------------------------------------------------
// Kernel 2: fused bilinear sampling (fp16 gather + HFMA2 combine) +
// single-fp16 HMMA GEMM.
// ---------------------------------------------------------------------------
__global__ __launch_bounds__(256, 2) void deform_main(
    const float* __restrict__ bias,
    float* __restrict__ out)
{
    extern __shared__ char ap[];
    uint32_t sbase = smem_u32(ap);

    short4* sposs = (short4*)(ap + POS_OFF);
    uint4*  swth  = (uint4*)(ap + WT_OFF);

    const int tid = threadIdx.x;
    const int cg = tid & 31;       // channel group (4 ch)
    const int pg = tid >> 5;       // pixel group (16 px)
    const int c0 = cg * 4;
    const int wid = tid >> 5;
    const int lane = tid & 31;
    const int wm = wid & 3;        // M quarter (32 px)
    const int nh = wid >> 2;       // N half (64 f)

    int pbase = blockIdx.x * MTILE;
    int b = pbase >> 12;
    int rem = pbase & 4095;
    int ybase = rem >> 6;

    // setup: clamped corner coords + validity-masked half2 bilinear weights
    for (int i = tid; i < MTILE * KKT; i += 256) {
        int t = i / KKT;
        int k = i - t * KKT;
        float dy = g_offsets[(size_t)(pbase + t) * OO + 2 * k];
        float dx = g_offsets[(size_t)(pbase + t) * OO + 2 * k + 1];
        float py = (float)(ybase + (t >> 6)) + (float)(k / 3 - 1) + dy;
        float px = (float)(t & 63) + (float)(k % 3 - 1) + dx;
        float fy = floorf(py), fx = floorf(px);
        int y0 = (int)fy, x0 = (int)fx;
        float wy = py - fy, wx = px - fx;
        bool vy0 = (unsigned)y0 < HH;
        bool vy1 = (unsigned)(y0 + 1) < HH;
        bool vx0 = (unsigned)x0 < WW;
        bool vx1 = (unsigned)(x0 + 1) < WW;
        float w00 = (vy0 && vx0) ? (1.f - wy) * (1.f - wx) : 0.f;
        float w01 = (vy0 && vx1) ? (1.f - wy) * wx : 0.f;
        float w10 = (vy1 && vx0) ? wy * (1.f - wx) : 0.f;
        float w11 = (vy1 && vx1) ? wy * wx : 0.f;
        int y0c = min(max(y0, 0), HH - 1);
        int y1c = min(max(y0 + 1, 0), HH - 1);
        int x0c = min(max(x0, 0), WW - 1);
        int x1c = min(max(x0 + 1, 0), WW - 1);
        sposs[i] = make_short4((short)y0c, (short)x0c, (short)y1c, (short)x1c);
        swth[i] = make_uint4(h2u(__float2half2_rn(w00)),
                             h2u(__float2half2_rn(w01)),
                             h2u(__float2half2_rn(w10)),
                             h2u(__float2half2_rn(w11)));
    }
    __syncthreads();

    float acc[2][8][4];
#pragma unroll
    for (int mt = 0; mt < 2; mt++)
#pragma unroll
        for (int nt = 0; nt < 8; nt++)
#pragma unroll
            for (int j = 0; j < 4; j++) acc[mt][nt][j] = 0.f;

    const __half* xh = g_xh + (size_t)b * HH * WW * CC;
    const int lrow = lane & 15;
    const int lch = lane >> 4;

    for (int k = 0; k < KKT; k++) {
        const uint32_t abuf = (k & 1) ? (uint32_t)A_B1 : (uint32_t)A_B0;

        // ---- Phase A: fp16 gathers (4 ch x 16 px per thread), HFMA2 ----
#pragma unroll 4
        for (int j = 0; j < 16; j++) {
            int t = pg * 16 + j;
            int i = t * KKT + k;
            short4 p = sposs[i];      // warp-broadcast
            uint4 wh = swth[i];       // warp-broadcast
            const __half* r0 = xh + ((int)p.x << 13) + c0;
            const __half* r1 = xh + ((int)p.z << 13) + c0;
            uint2 v00 = *(const uint2*)(r0 + ((int)p.y << 7));
            uint2 v01 = *(const uint2*)(r0 + ((int)p.w << 7));
            uint2 v10 = *(const uint2*)(r1 + ((int)p.y << 7));
            uint2 v11 = *(const uint2*)(r1 + ((int)p.w << 7));
            __half2 s01 = __hmul2(u2h(v00.x), u2h(wh.x));
            __half2 s23 = __hmul2(u2h(v00.y), u2h(wh.x));
            s01 = __hfma2(u2h(v01.x), u2h(wh.y), s01);
            s23 = __hfma2(u2h(v01.y), u2h(wh.y), s23);
            s01 = __hfma2(u2h(v10.x), u2h(wh.z), s01);
            s23 = __hfma2(u2h(v10.y), u2h(wh.z), s23);
            s01 = __hfma2(u2h(v11.x), u2h(wh.w), s01);
            s23 = __hfma2(u2h(v11.y), u2h(wh.w), s23);
            uint32_t off = (uint32_t)t * 256u
                         + ((((uint32_t)c0 >> 3) ^ ((uint32_t)t & 7)) << 4)
                         + ((uint32_t)c0 & 7) * 2u;
            *(uint2*)(ap + abuf + off) = make_uint2(h2u(s01), h2u(s23));
        }
        __syncthreads();

        // ---- Phase B: 8 k-chunks of 16, single product ----
#pragma unroll
        for (int kc = 0; kc < 8; kc++) {
            uint32_t ah[2][4];
#pragma unroll
            for (int mt = 0; mt < 2; mt++) {
                int row = wm * 32 + mt * 16 + lrow;
                uint32_t chunk = (uint32_t)(kc * 2 + lch);
                uint32_t off = (uint32_t)row * 256u
                             + ((chunk ^ ((uint32_t)row & 7)) << 4);
                LDM4(ah[mt][0], ah[mt][1], ah[mt][2], ah[mt][3], sbase + abuf + off);
            }
            size_t bidx = ((((size_t)k * 8 + kc) * 2 + nh) * 4) * 32 + lane;

            const uint4* bb = ((const uint4*)g_bfhi) + bidx;
            uint4 bf0 = bb[0], bf1 = bb[32], bf2 = bb[64], bf3 = bb[96];
            uint32_t br[16] = { bf0.x, bf0.y, bf0.z, bf0.w,
                                bf1.x, bf1.y, bf1.z, bf1.w,
                                bf2.x, bf2.y, bf2.z, bf2.w,
                                bf3.x, bf3.y, bf3.z, bf3.w };
#pragma unroll
            for (int mt = 0; mt < 2; mt++)
#pragma unroll
                for (int nt = 0; nt < 8; nt++)
                    MMA16816(acc[mt][nt][0], acc[mt][nt][1], acc[mt][nt][2], acc[mt][nt][3],
                             ah[mt][0], ah[mt][1], ah[mt][2], ah[mt][3],
                             br[nt * 2], br[nt * 2 + 1]);
        }
        __syncthreads();
    }

    // ---- epilogue: bias + store ----
#pragma unroll
    for (int mt = 0; mt < 2; mt++) {
        int row0 = pbase + wm * 32 + mt * 16 + (lane >> 2);
#pragma unroll
        for (int nt = 0; nt < 8; nt++) {
            int col = nh * 64 + nt * 8 + (lane & 3) * 2;
            float2 bv = *(const float2*)(bias + col);
            *(float2*)(out + (size_t)row0 * FF + col) =
                make_float2(acc[mt][nt][0] + bv.x, acc[mt][nt][1] + bv.y);
            *(float2*)(out + (size_t)(row0 + 8) * FF + col) =
                make_float2(acc[mt][nt][2] + bv.x, acc[mt][nt][3] + bv.y);
        }
    }
}

// ---------------------------------------------------------------------------
extern "C" void kernel_launch(void* const* d_in, const int* in_sizes, int n_in,
                              void* d_out, int out_size)
{
    const float* x        = (const float*)d_in[0];
    const float* kern     = (const float*)d_in[1];
    const float* bias     = (const float*)d_in[2];
    const float* offset_w = (const float*)d_in[3];
    const float* offset_b = (const float*)d_in[4];
    float* out = (float*)d_out;

    cudaFuncSetAttribute(deform_main,
                         cudaFuncAttributeMaxDynamicSharedMemorySize, DYN_SMEM);
    cudaFuncSetAttribute(offsets_hmma,
                         cudaFuncAttributeMaxDynamicSharedMemorySize, OFF_SMEM);

    noop_align<<<1, 32>>>();
    prep_weights<<<(BFRAG_N + 255) / 256, 256>>>(kern, offset_w);
    offsets_hmma<<<(BB * HH * WW) / MTILE, 256, OFF_SMEM>>>(x, offset_b);
    deform_main<<<(BB * HH * WW) / MTILE, 256, DYN_SMEM>>>(bias, out);
}

// round 17
// speedup vs baseline: 1.1123x; 1.1123x over previous
#include <cuda_runtime.h>
#include <cuda_fp16.h>
#include <cstdint>

// Problem constants
#define BB 8
#define HH 64
#define WW 64
#define CC 128
#define FF 128
#define KKT 9
#define OO 18
#define MTILE 128           // pixels per CTA (= GEMM M)

// deform_main dynamic SMEM layout (byte offsets)
#define A_B0 0
#define A_B1 32768
#define POS_OFF 65536                      // short4[1152] = 9216 B
#define WT_OFF  (POS_OFF + 9216)           // uint4[1152] = 18432 B
#define DYN_SMEM (WT_OFF + 18432)          // 93184 B
// offsets_hmma dynamic SMEM: two 32 KB A buffers
#define OFF_SMEM 65536

// scratch (no allocation allowed)
__device__ float g_offsets[BB * HH * WW * OO];     // [pix][18]
__device__ __half g_xh[BB * HH * WW * CC];         // fp16 mirror of x
// main-GEMM B fragments, HMMA-register layout (single fp16):
// [tap][kc][nh][i(4)][lane(32)] as uint4
#define BFRAG_N (KKT * 8 * 2 * 4 * 32 * 4)
__device__ uint32_t g_bfhi[BFRAG_N];
// offset-GEMM B fragments (N=32 padded from 18): [tap][kc][i(2)][lane] uint4
#define OBF_N (KKT * 8 * 2 * 32 * 4)
__device__ uint32_t g_obfhi[OBF_N];

// ---------------------------------------------------------------------------
static __device__ __forceinline__ uint32_t h2u(__half2 h) {
    return *reinterpret_cast<uint32_t*>(&h);
}
static __device__ __forceinline__ __half2 u2h(uint32_t u) {
    return *reinterpret_cast<__half2*>(&u);
}

static __device__ __forceinline__ uint32_t smem_u32(const void* p) {
    uint32_t a;
    asm("{ .reg .u64 t; cvta.to.shared.u64 t, %1; cvt.u32.u64 %0, t; }"
        : "=r"(a) : "l"(p));
    return a;
}

#define LDM4(r0, r1, r2, r3, addr) \
    asm("ldmatrix.sync.aligned.m8n8.x4.shared.b16 {%0,%1,%2,%3}, [%4];" \
        : "=r"(r0), "=r"(r1), "=r"(r2), "=r"(r3) : "r"(addr))

#define MMA16816(c0, c1, c2, c3, a0, a1, a2, a3, b0, b1) \
    asm("mma.sync.aligned.m16n8k16.row.col.f32.f16.f16.f32 " \
        "{%0,%1,%2,%3}, {%4,%5,%6,%7}, {%8,%9}, {%0,%1,%2,%3};" \
        : "+f"(c0), "+f"(c1), "+f"(c2), "+f"(c3) \
        : "r"(a0), "r"(a1), "r"(a2), "r"(a3), "r"(b0), "r"(b1))

// ---------------------------------------------------------------------------
// Kernel 0: x -> fp16 mirror (also keeps ncu launch alignment: 4 launches).
// ---------------------------------------------------------------------------
#define XN4 (BB * HH * WW * CC / 4)
__global__ __launch_bounds__(256) void convert_x(const float* __restrict__ x) {
    const float4* s4 = (const float4*)x;
    uint2* d2 = (uint2*)g_xh;
    for (int i = blockIdx.x * 256 + threadIdx.x; i < XN4; i += gridDim.x * 256) {
        float4 v = s4[i];
        d2[i] = make_uint2(h2u(__floats2half2_rn(v.x, v.y)),
                           h2u(__floats2half2_rn(v.z, v.w)));
    }
}

// ---------------------------------------------------------------------------
// Kernel 1: prep — fp16 B-fragment packing (single fp16 for both GEMMs).
// ---------------------------------------------------------------------------
__global__ void prep_weights(const float* __restrict__ kern,
                             const float* __restrict__ ow) {
    int idx = blockIdx.x * 256 + threadIdx.x;
    if (idx < BFRAG_N) {
        int j    = idx & 3;
        int lane = (idx >> 2) & 31;
        int i    = (idx >> 7) & 3;
        int nh   = (idx >> 9) & 1;
        int kc   = (idx >> 10) & 7;
        int tap  = idx >> 13;
        int nt    = i * 2 + (j >> 1);
        int which = j & 1;
        int n = nh * 64 + nt * 8 + (lane >> 2);
        int k = kc * 16 + which * 8 + (lane & 3) * 2;
        float w0 = kern[((size_t)tap * CC + k) * FF + n];
        float w1 = kern[((size_t)tap * CC + k + 1) * FF + n];
        g_bfhi[idx] = h2u(__floats2half2_rn(w0, w1));
    }
    if (idx < OBF_N) {
        int j    = idx & 3;
        int lane = (idx >> 2) & 31;
        int i    = (idx >> 7) & 1;
        int kc   = (idx >> 8) & 7;
        int tap  = idx >> 11;
        int nt    = i * 2 + (j >> 1);
        int which = j & 1;
        int n = nt * 8 + (lane >> 2);
        int k = kc * 16 + which * 8 + (lane & 3) * 2;
        float w0 = 0.f, w1 = 0.f;
        if (n < OO) {
            w0 = ow[((size_t)tap * CC + k) * OO + n];
            w1 = ow[((size_t)tap * CC + k + 1) * OO + n];
        }
        g_obfhi[idx] = h2u(__floats2half2_rn(w0, w1));
    }
}

// ---------------------------------------------------------------------------
// Kernel 2: offset-predicting 3x3 conv via HMMA (single fp16 B, 3 n-tiles).
// ---------------------------------------------------------------------------
__global__ __launch_bounds__(256) void offsets_hmma(
    const float* __restrict__ x,
    const float* __restrict__ ob)
{
    extern __shared__ char ap[];
    uint32_t sbase = smem_u32(ap);

    const int tid = threadIdx.x;
    const int cg = tid & 31;
    const int pg = tid >> 5;
    const int c0 = cg * 4;
    const int wid = tid >> 5;
    const int lane = tid & 31;
    const int lrow = lane & 15;
    const int lch = lane >> 4;

    int pbase = blockIdx.x * MTILE;
    int b = pbase >> 12;
    int ybase = (pbase & 4095) >> 6;

    const float* xb = x + (size_t)b * HH * WW * CC;

    float acc[3][4];
#pragma unroll
    for (int nt = 0; nt < 3; nt++)
#pragma unroll
        for (int j = 0; j < 4; j++) acc[nt][j] = 0.f;

    for (int k = 0; k < KKT; k++) {
        const uint32_t abuf = (k & 1) ? (uint32_t)A_B1 : (uint32_t)A_B0;
        int dyk = k / 3 - 1, dxk = k % 3 - 1;

#pragma unroll 4
        for (int j = 0; j < 16; j++) {
            int t = pg * 16 + j;
            int iy = ybase + (t >> 6) + dyk;
            int ix = (t & 63) + dxk;
            float4 v = make_float4(0.f, 0.f, 0.f, 0.f);
            if ((unsigned)iy < HH && (unsigned)ix < WW)
                v = *(const float4*)(xb + ((iy << 6) + ix) * CC + c0);
            uint32_t off = (uint32_t)t * 256u
                         + ((((uint32_t)c0 >> 3) ^ ((uint32_t)t & 7)) << 4)
                         + ((uint32_t)c0 & 7) * 2u;
            *(uint2*)(ap + abuf + off) =
                make_uint2(h2u(__floats2half2_rn(v.x, v.y)),
                           h2u(__floats2half2_rn(v.z, v.w)));
        }
        __syncthreads();

#pragma unroll
        for (int kc = 0; kc < 8; kc++) {
            int row = wid * 16 + lrow;
            uint32_t chunk = (uint32_t)(kc * 2 + lch);
            uint32_t aoff = (uint32_t)row * 256u
                          + ((chunk ^ ((uint32_t)row & 7)) << 4);
            uint32_t a0, a1, a2, a3;
            LDM4(a0, a1, a2, a3, sbase + abuf + aoff);

            size_t bidx = (((size_t)k * 8 + kc) * 2) * 32 + lane;
            const uint4* bh = ((const uint4*)g_obfhi) + bidx;
            uint4 bh0 = bh[0], bh1 = bh[32];
            uint32_t brh[6] = { bh0.x, bh0.y, bh0.z, bh0.w, bh1.x, bh1.y };
#pragma unroll
            for (int nt = 0; nt < 3; nt++)
                MMA16816(acc[nt][0], acc[nt][1], acc[nt][2], acc[nt][3],
                         a0, a1, a2, a3, brh[nt * 2], brh[nt * 2 + 1]);
        }
    }

    {
        int r0 = pbase + wid * 16 + (lane >> 2);
#pragma unroll
        for (int nt = 0; nt < 3; nt++) {
            int col = nt * 8 + (lane & 3) * 2;
            if (col < OO) {
                float2 ob2 = *(const float2*)(ob + col);
                *(float2*)(g_offsets + (size_t)r0 * OO + col) =
                    make_float2(acc[nt][0] + ob2.x, acc[nt][1] + ob2.y);
                *(float2*)(g_offsets + (size_t)(r0 + 8) * OO + col) =
                    make_float2(acc[nt][2] + ob2.x, acc[nt][3] + ob2.y);
            }
        }
    }
}

// ---------------------------------------------------------------------------
// Kernel 3: fused bilinear sampling (fp16 gather + HFMA2 combine) +
// single-fp16 HMMA GEMM (unchanged from R16).
// ---------------------------------------------------------------------------
__global__ __launch_bounds__(256, 2) void deform_main(
    const float* __restrict__ bias,
    float* __restrict__ out)
{
    extern __shared__ char ap[];
    uint32_t sbase = smem_u32(ap);

    short4* sposs = (short4*)(ap + POS_OFF);
    uint4*  swth  = (uint4*)(ap + WT_OFF);

    const int tid = threadIdx.x;
    const int cg = tid & 31;       // channel group (4 ch)
    const int pg = tid >> 5;       // pixel group (16 px)
    const int c0 = cg * 4;
    const int wid = tid >> 5;
    const int lane = tid & 31;
    const int wm = wid & 3;        // M quarter (32 px)
    const int nh = wid >> 2;       // N half (64 f)

    int pbase = blockIdx.x * MTILE;
    int b = pbase >> 12;
    int rem = pbase & 4095;
    int ybase = rem >> 6;

    // setup: clamped corner coords + validity-masked half2 bilinear weights
    for (int i = tid; i < MTILE * KKT; i += 256) {
        int t = i / KKT;
        int k = i - t * KKT;
        float dy = g_offsets[(size_t)(pbase + t) * OO + 2 * k];
        float dx = g_offsets[(size_t)(pbase + t) * OO + 2 * k + 1];
        float py = (float)(ybase + (t >> 6)) + (float)(k / 3 - 1) + dy;
        float px = (float)(t & 63) + (float)(k % 3 - 1) + dx;
        float fy = floorf(py), fx = floorf(px);
        int y0 = (int)fy, x0 = (int)fx;
        float wy = py - fy, wx = px - fx;
        bool vy0 = (unsigned)y0 < HH;
        bool vy1 = (unsigned)(y0 + 1) < HH;
        bool vx0 = (unsigned)x0 < WW;
        bool vx1 = (unsigned)(x0 + 1) < WW;
        float w00 = (vy0 && vx0) ? (1.f - wy) * (1.f - wx) : 0.f;
        float w01 = (vy0 && vx1) ? (1.f - wy) * wx : 0.f;
        float w10 = (vy1 && vx0) ? wy * (1.f - wx) : 0.f;
        float w11 = (vy1 && vx1) ? wy * wx : 0.f;
        int y0c = min(max(y0, 0), HH - 1);
        int y1c = min(max(y0 + 1, 0), HH - 1);
        int x0c = min(max(x0, 0), WW - 1);
        int x1c = min(max(x0 + 1, 0), WW - 1);
        sposs[i] = make_short4((short)y0c, (short)x0c, (short)y1c, (short)x1c);
        swth[i] = make_uint4(h2u(__float2half2_rn(w00)),
                             h2u(__float2half2_rn(w01)),
                             h2u(__float2half2_rn(w10)),
                             h2u(__float2half2_rn(w11)));
    }
    __syncthreads();

    float acc[2][8][4];
#pragma unroll
    for (int mt = 0; mt < 2; mt++)
#pragma unroll
        for (int nt = 0; nt < 8; nt++)
#pragma unroll
            for (int j = 0; j < 4; j++) acc[mt][nt][j] = 0.f;

    const __half* xh = g_xh + (size_t)b * HH * WW * CC;
    const int lrow = lane & 15;
    const int lch = lane >> 4;

    for (int k = 0; k < KKT; k++) {
        const uint32_t abuf = (k & 1) ? (uint32_t)A_B1 : (uint32_t)A_B0;

        // ---- Phase A: fp16 gathers (4 ch x 16 px per thread), HFMA2 ----
#pragma unroll 4
        for (int j = 0; j < 16; j++) {
            int t = pg * 16 + j;
            int i = t * KKT + k;
            short4 p = sposs[i];      // warp-broadcast
            uint4 wh = swth[i];       // warp-broadcast
            const __half* r0 = xh + ((int)p.x << 13) + c0;
            const __half* r1 = xh + ((int)p.z << 13) + c0;
            uint2 v00 = *(const uint2*)(r0 + ((int)p.y << 7));
            uint2 v01 = *(const uint2*)(r0 + ((int)p.w << 7));
            uint2 v10 = *(const uint2*)(r1 + ((int)p.y << 7));
            uint2 v11 = *(const uint2*)(r1 + ((int)p.w << 7));
            __half2 s01 = __hmul2(u2h(v00.x), u2h(wh.x));
            __half2 s23 = __hmul2(u2h(v00.y), u2h(wh.x));
            s01 = __hfma2(u2h(v01.x), u2h(wh.y), s01);
            s23 = __hfma2(u2h(v01.y), u2h(wh.y), s23);
            s01 = __hfma2(u2h(v10.x), u2h(wh.z), s01);
            s23 = __hfma2(u2h(v10.y), u2h(wh.z), s23);
            s01 = __hfma2(u2h(v11.x), u2h(wh.w), s01);
            s23 = __hfma2(u2h(v11.y), u2h(wh.w), s23);
            uint32_t off = (uint32_t)t * 256u
                         + ((((uint32_t)c0 >> 3) ^ ((uint32_t)t & 7)) << 4)
                         + ((uint32_t)c0 & 7) * 2u;
            *(uint2*)(ap + abuf + off) = make_uint2(h2u(s01), h2u(s23));
        }
        __syncthreads();

        // ---- Phase B: 8 k-chunks of 16, single product ----
#pragma unroll
        for (int kc = 0; kc < 8; kc++) {
            uint32_t ah[2][4];
#pragma unroll
            for (int mt = 0; mt < 2; mt++) {
                int row = wm * 32 + mt * 16 + lrow;
                uint32_t chunk = (uint32_t)(kc * 2 + lch);
                uint32_t off = (uint32_t)row * 256u
                             + ((chunk ^ ((uint32_t)row & 7)) << 4);
                LDM4(ah[mt][0], ah[mt][1], ah[mt][2], ah[mt][3], sbase + abuf + off);
            }
            size_t bidx = ((((size_t)k * 8 + kc) * 2 + nh) * 4) * 32 + lane;

            const uint4* bb = ((const uint4*)g_bfhi) + bidx;
            uint4 bf0 = bb[0], bf1 = bb[32], bf2 = bb[64], bf3 = bb[96];
            uint32_t br[16] = { bf0.x, bf0.y, bf0.z, bf0.w,
                                bf1.x, bf1.y, bf1.z, bf1.w,
                                bf2.x, bf2.y, bf2.z, bf2.w,
                                bf3.x, bf3.y, bf3.z, bf3.w };
#pragma unroll
            for (int mt = 0; mt < 2; mt++)
#pragma unroll
                for (int nt = 0; nt < 8; nt++)
                    MMA16816(acc[mt][nt][0], acc[mt][nt][1], acc[mt][nt][2], acc[mt][nt][3],
                             ah[mt][0], ah[mt][1], ah[mt][2], ah[mt][3],
                             br[nt * 2], br[nt * 2 + 1]);
        }
        __syncthreads();
    }

    // ---- epilogue: bias + store ----
#pragma unroll
    for (int mt = 0; mt < 2; mt++) {
        int row0 = pbase + wm * 32 + mt * 16 + (lane >> 2);
#pragma unroll
        for (int nt = 0; nt < 8; nt++) {
            int col = nh * 64 + nt * 8 + (lane & 3) * 2;
            float2 bv = *(const float2*)(bias + col);
            *(float2*)(out + (size_t)row0 * FF + col) =
                make_float2(acc[mt][nt][0] + bv.x, acc[mt][nt][1] + bv.y);
            *(float2*)(out + (size_t)(row0 + 8) * FF + col) =
                make_float2(acc[mt][nt][2] + bv.x, acc[mt][nt][3] + bv.y);
        }
    }
}

// ---------------------------------------------------------------------------
extern "C" void kernel_launch(void* const* d_in, const int* in_sizes, int n_in,
                              void* d_out, int out_size)
{
    const float* x        = (const float*)d_in[0];
    const float* kern     = (const float*)d_in[1];
    const float* bias     = (const float*)d_in[2];
    const float* offset_w = (const float*)d_in[3];
    const float* offset_b = (const float*)d_in[4];
    float* out = (float*)d_out;

    cudaFuncSetAttribute(deform_main,
                         cudaFuncAttributeMaxDynamicSharedMemorySize, DYN_SMEM);
    cudaFuncSetAttribute(offsets_hmma,
                         cudaFuncAttributeMaxDynamicSharedMemorySize, OFF_SMEM);

    convert_x<<<592, 256>>>(x);
    prep_weights<<<(BFRAG_N + 255) / 256, 256>>>(kern, offset_w);
    offsets_hmma<<<(BB * HH * WW) / MTILE, 256, OFF_SMEM>>>(x, offset_b);
    deform_main<<<(BB * HH * WW) / MTILE, 256, DYN_SMEM>>>(bias, out);
}